// round 2
// baseline (speedup 1.0000x reference)
#include <cuda_runtime.h>
#include <cuda_bf16.h>
#include <cstdint>

// Problem constants
#define BATCH 128
#define NN    128           // nodes per graph
#define D_IN  6
#define HDIM  32
#define D_MP  64
#define TOTAL (BATCH*NN)    // 16384
#define U_STRIDE 512        // 4*N
#define U_PER_B  (512*512)  // 262144

__device__ float g_A0[TOTAL*128];   // h @ We0[:64]
__device__ float g_B0[TOTAL*128];   // h @ We0[64:]

__device__ __forceinline__ float lrelu(float v){ return v >= 0.f ? v : 0.1f*v; }

// ---------------------------------------------------------------------------
// K1: 3-layer GCN on complete graph. One block per batch, 128 threads = nodes.
// gcn(h,W,b)[n] = (S - (hW)[n])/127 + b, S = batch sum of hW.
// ---------------------------------------------------------------------------
__global__ void k1_gcn(const float* __restrict__ x,
                       const float* __restrict__ Wg0, const float* __restrict__ bg0,
                       const float* __restrict__ Wg1, const float* __restrict__ bg1,
                       const float* __restrict__ Wg2, const float* __restrict__ bg2,
                       float* __restrict__ h_out)
{
    __shared__ float buf[128*65];   // padded stride 65 (bank-conflict free)
    __shared__ float S[64];
    const int n = threadIdx.x;
    const int base = blockIdx.x * NN;
    const float inv = 1.0f/127.0f;

    float xr[D_IN];
#pragma unroll
    for (int k=0;k<D_IN;k++) xr[k] = x[(base+n)*D_IN + k];

    float y[64];

    // ---- layer 0: D_IN -> 32, lrelu ----
#pragma unroll
    for (int c=0;c<32;c++){
        float a = 0.f;
#pragma unroll
        for (int k=0;k<D_IN;k++) a += xr[k]*__ldg(&Wg0[k*32+c]);
        y[c]=a; buf[n*65+c]=a;
    }
    __syncthreads();
    if (n<32){ float s=0.f; for(int m=0;m<128;m++) s += buf[m*65+n]; S[n]=s; }
    __syncthreads();
#pragma unroll
    for (int c=0;c<32;c++) buf[n*65+c] = lrelu((S[c]-y[c])*inv + __ldg(&bg0[c]));
    __syncthreads();

    // ---- layer 1: 32 -> 32, lrelu ----
#pragma unroll
    for (int c=0;c<32;c++){
        float a = 0.f;
#pragma unroll
        for (int k=0;k<32;k++) a += buf[n*65+k]*__ldg(&Wg1[k*32+c]);
        y[c]=a;
    }
    __syncthreads();
#pragma unroll
    for (int c=0;c<32;c++) buf[n*65+c]=y[c];
    __syncthreads();
    if (n<32){ float s=0.f; for(int m=0;m<128;m++) s += buf[m*65+n]; S[n]=s; }
    __syncthreads();
#pragma unroll
    for (int c=0;c<32;c++) buf[n*65+c] = lrelu((S[c]-y[c])*inv + __ldg(&bg1[c]));
    __syncthreads();

    // ---- layer 2: 32 -> 64, no activation ----
#pragma unroll
    for (int c=0;c<64;c++){
        float a = 0.f;
#pragma unroll
        for (int k=0;k<32;k++) a += buf[n*65+k]*__ldg(&Wg2[k*64+c]);
        y[c]=a;
    }
    __syncthreads();
#pragma unroll
    for (int c=0;c<64;c++) buf[n*65+c]=y[c];
    __syncthreads();
    if (n<64){ float s=0.f; for(int m=0;m<128;m++) s += buf[m*65+n]; S[n]=s; }
    __syncthreads();
#pragma unroll
    for (int c=0;c<64;c++)
        h_out[(base+n)*64 + c] = (S[c]-y[c])*inv + __ldg(&bg2[c]);
}

// ---------------------------------------------------------------------------
// K2: A0 = h @ We0[:64,:], B0 = h @ We0[64:,:].  Block: 32 nodes, 256 threads
// (thread = output column; 128 A-cols then 128 B-cols).
// ---------------------------------------------------------------------------
__global__ void k2_ab(const float* __restrict__ h, const float* __restrict__ We0)
{
    __shared__ float hs[32*64];
    const int tid = threadIdx.x;
    const int n0 = blockIdx.x * 32;

    for (int l = tid; l < 32*64; l += 256) hs[l] = h[n0*64 + l];
    __syncthreads();

    const int col = tid & 127;
    const int kb  = (tid >> 7) * 64;   // 0 -> A0 (rows 0..63), 1 -> B0 (rows 64..127)

    float acc[32];
#pragma unroll
    for (int i=0;i<32;i++) acc[i]=0.f;

    for (int k=0;k<64;k++){
        float w = __ldg(&We0[(kb+k)*128 + col]);
#pragma unroll
        for (int nn=0;nn<32;nn++) acc[nn] += hs[nn*64+k]*w;   // broadcast LDS
    }

    float* dst = (tid < 128) ? g_A0 : g_B0;
#pragma unroll
    for (int nn=0;nn<32;nn++) dst[(size_t)(n0+nn)*128 + col] = acc[nn];
}

// ---------------------------------------------------------------------------
// K2b: node MLP 64->64->64->10 + diagonal 4x4 blocks of U.
// One block per batch, thread = node, weights staged in shared.
// ---------------------------------------------------------------------------
__global__ void k2b_node(const float* __restrict__ h,
                         const float* __restrict__ Wn0, const float* __restrict__ bn0,
                         const float* __restrict__ Wn1, const float* __restrict__ bn1,
                         const float* __restrict__ Wn2, const float* __restrict__ bn2,
                         float* __restrict__ U)
{
    __shared__ float w0[64*64], w1[64*64], w2[64*10];
    __shared__ float b0s[64], b1s[64], b2s[10];
    const int n = threadIdx.x;
    const int b = blockIdx.x;

    for (int l=n; l<4096; l+=128){ w0[l]=Wn0[l]; w1[l]=Wn1[l]; }
    for (int l=n; l<640;  l+=128) w2[l]=Wn2[l];
    if (n<64){ b0s[n]=bn0[n]; b1s[n]=bn1[n]; }
    if (n<10) b2s[n]=bn2[n];
    __syncthreads();

    const float* hr = h + (size_t)(b*NN+n)*64;
    float h0[64];
#pragma unroll
    for (int k=0;k<64;k++) h0[k]=hr[k];

    float t1[64];
#pragma unroll
    for (int c=0;c<64;c++){
        float a=b0s[c];
#pragma unroll
        for (int k=0;k<64;k++) a += h0[k]*w0[k*64+c];
        t1[c]=lrelu(a);
    }
    float t2[64];
#pragma unroll
    for (int c=0;c<64;c++){
        float a=b1s[c];
#pragma unroll
        for (int k=0;k<64;k++) a += t1[k]*w1[k*64+c];
        t2[c]=lrelu(a);
    }
    float v[10];
#pragma unroll
    for (int c=0;c<10;c++){
        float a=b2s[c];
#pragma unroll
        for (int k=0;k<64;k++) a += t2[k]*w2[k*10+c];
        v[c]=a;
    }

    const int SMAT[16] = {0,1,2,3, 1,4,5,6, 2,5,7,8, 3,6,8,9};
    float* Ub = U + (size_t)b*U_PER_B;
#pragma unroll
    for (int a=0;a<4;a++){
        float4 r;
        r.x = v[SMAT[a*4+0]]; r.y = v[SMAT[a*4+1]];
        r.z = v[SMAT[a*4+2]]; r.w = v[SMAT[a*4+3]];
        *reinterpret_cast<float4*>(Ub + (size_t)(4*n+a)*U_STRIDE + 4*n) = r;
    }
}

// ---------------------------------------------------------------------------
// K3: edge MLP (layers 1,2 per-pair) + scatter into U off-diagonal blocks.
// Grid (16,16,128): blockIdx.y = i-tile, blockIdx.x = j-tile, z = batch.
// 8x8 pair tile (64 pairs), 256 threads, shared-memory GEMMs.
// ---------------------------------------------------------------------------
#define K3_SMEM_FLOATS (2*64*130 + 32*132)
#define K3_SMEM_BYTES  (K3_SMEM_FLOATS*4)

__global__ void k3_edge(const float* __restrict__ be0,
                        const float* __restrict__ We1, const float* __restrict__ be1,
                        const float* __restrict__ We2, const float* __restrict__ be2,
                        float* __restrict__ U)
{
    if (blockIdx.y > blockIdx.x) return;   // only i-tile <= j-tile

    extern __shared__ float smem[];
    float* t0s = smem;                 // [64][130]
    float* t1s = smem + 64*130;        // [64][130]
    float* ws  = smem + 2*64*130;      // [32][132] staging / We2
    float* A0s = t1s;                  // alias (t1s unused until epilogue)
    float* B0s = t1s + 8*128;

    const int tid = threadIdx.x;
    const int b  = blockIdx.z;
    const int i0 = blockIdx.y * 8;
    const int j0 = blockIdx.x * 8;

    // ---- stage A0 (8 rows) and B0 (8 rows) ----
#pragma unroll
    for (int l = tid; l < 512; l += 256){            // 512 float4s
        int half = l >> 8;                           // 0: A0, 1: B0
        int r = (l >> 5) & 7, c4 = l & 31;
        const float* src = half ? (g_B0 + (size_t)(b*NN + j0 + r)*128)
                                : (g_A0 + (size_t)(b*NN + i0 + r)*128);
        float4 v = *reinterpret_cast<const float4*>(src + c4*4);
        float* dst = half ? B0s : A0s;
        *reinterpret_cast<float4*>(dst + r*128 + c4*4) = v;
    }
    __syncthreads();

    // ---- t0[p][k] = lrelu(A0[i] + B0[j] + be0) ----
#pragma unroll
    for (int e = tid; e < 64*128; e += 256){
        int p = e >> 7, k = e & 127;
        int ii = p >> 3, jj = p & 7;
        t0s[p*130 + k] = lrelu(A0s[ii*128+k] + B0s[jj*128+k] + __ldg(&be0[k]));
    }
    __syncthreads();

    // ---- GEMM1: t1 = lrelu(t0[64x128] @ We1[128x128] + be1) ----
    const int tr = tid >> 4;      // 0..15 -> rows tr*4..+3
    const int tc = tid & 15;      // 0..15 -> cols tc*8..+7
    float acc[4][8];
#pragma unroll
    for (int r=0;r<4;r++)
#pragma unroll
        for (int c=0;c<8;c++) acc[r][c]=0.f;

    for (int kb = 0; kb < 128; kb += 32){
#pragma unroll
        for (int l = tid; l < 1024; l += 256){       // 32 rows x 32 float4
            int r = l >> 5, c4 = l & 31;
            float4 w = *reinterpret_cast<const float4*>(We1 + (size_t)(kb+r)*128 + c4*4);
            *reinterpret_cast<float4*>(ws + r*132 + c4*4) = w;
        }
        __syncthreads();
#pragma unroll 8
        for (int kk = 0; kk < 32; ++kk){
            float a[4];
#pragma unroll
            for (int r=0;r<4;r++) a[r] = t0s[(tr*4+r)*130 + kb + kk];
            float4 bv0 = *reinterpret_cast<const float4*>(ws + kk*132 + tc*8);
            float4 bv1 = *reinterpret_cast<const float4*>(ws + kk*132 + tc*8 + 4);
            float bvf[8] = {bv0.x,bv0.y,bv0.z,bv0.w, bv1.x,bv1.y,bv1.z,bv1.w};
#pragma unroll
            for (int r=0;r<4;r++)
#pragma unroll
                for (int c=0;c<8;c++) acc[r][c] += a[r]*bvf[c];
        }
        __syncthreads();
    }
#pragma unroll
    for (int r=0;r<4;r++){
        int row = tr*4+r;
#pragma unroll
        for (int c=0;c<8;c++){
            int col = tc*8+c;
            t1s[row*130+col] = lrelu(acc[r][c] + __ldg(&be1[col]));
        }
    }
    // stage We2 into ws (linear [128*16])
#pragma unroll
    for (int l = tid; l < 128*16; l += 256) ws[l] = __ldg(&We2[l]);
    __syncthreads();

    // ---- GEMM2 + scatter: e = t1 @ We2 + be2; 4 threads per pair ----
    const int p = tid >> 2;     // pair 0..63
    const int q = tid & 3;      // row of 4x4 block
    float4 e = *reinterpret_cast<const float4*>(be2 + q*4);
#pragma unroll 8
    for (int k = 0; k < 128; ++k){
        float v = t1s[p*130 + k];
        float4 w = *reinterpret_cast<const float4*>(ws + k*16 + q*4);
        e.x += v*w.x; e.y += v*w.y; e.z += v*w.z; e.w += v*w.w;
    }
    const int i = i0 + (p >> 3);
    const int j = j0 + (p & 7);
    if (i < j){
        float* Ub = U + (size_t)b*U_PER_B;
        *reinterpret_cast<float4*>(Ub + (size_t)(4*i+q)*U_STRIDE + 4*j) = e;
        *reinterpret_cast<float4*>(Ub + (size_t)(4*j+q)*U_STRIDE + 4*i) = e;
    }
}

// ---------------------------------------------------------------------------
extern "C" void kernel_launch(void* const* d_in, const int* in_sizes, int n_in,
                              void* d_out, int out_size)
{
    const float* x   = (const float*)d_in[0];
    // d_in[1]=edge_index, d_in[2]=edge_map, d_in[3]=ud_edges: structure is the
    // known complete graph; not needed at runtime.
    const float* Wg0 = (const float*)d_in[4];
    const float* bg0 = (const float*)d_in[5];
    const float* Wg1 = (const float*)d_in[6];
    const float* bg1 = (const float*)d_in[7];
    const float* Wg2 = (const float*)d_in[8];
    const float* bg2 = (const float*)d_in[9];
    const float* Wn0 = (const float*)d_in[10];
    const float* bn0 = (const float*)d_in[11];
    const float* Wn1 = (const float*)d_in[12];
    const float* bn1 = (const float*)d_in[13];
    const float* Wn2 = (const float*)d_in[14];
    const float* bn2 = (const float*)d_in[15];
    const float* We0 = (const float*)d_in[16];
    const float* be0 = (const float*)d_in[17];
    const float* We1 = (const float*)d_in[18];
    const float* be1 = (const float*)d_in[19];
    const float* We2 = (const float*)d_in[20];
    const float* be2 = (const float*)d_in[21];

    float* h_out = (float*)d_out;                     // (16384, 64)
    float* U     = h_out + (size_t)TOTAL*D_MP;        // (128, 512, 512)

    cudaFuncSetAttribute(k3_edge, cudaFuncAttributeMaxDynamicSharedMemorySize,
                         K3_SMEM_BYTES);

    k1_gcn<<<BATCH, 128>>>(x, Wg0,bg0, Wg1,bg1, Wg2,bg2, h_out);
    k2_ab<<<TOTAL/32, 256>>>(h_out, We0);
    k2b_node<<<BATCH, 128>>>(h_out, Wn0,bn0, Wn1,bn1, Wn2,bn2, U);
    k3_edge<<<dim3(16,16,BATCH), 256, K3_SMEM_BYTES>>>(be0, We1, be1, We2, be2, U);
}

// round 4
// speedup vs baseline: 2.0835x; 2.0835x over previous
#include <cuda_runtime.h>
#include <cuda_bf16.h>
#include <cstdint>

// Problem constants
#define BATCH 128
#define NN    128
#define D_IN  6
#define D_MP  64
#define TOTAL (BATCH*NN)    // 16384
#define U_STRIDE 512
#define U_PER_B  (512*512)

__device__ float g_A0[TOTAL*128];           // h @ We0[:64]
__device__ float g_B0[TOTAL*128];           // h @ We0[64:]
__device__ __nv_bfloat16 g_Bhi[128*136];    // We1^T hi, padded [n][136]
__device__ __nv_bfloat16 g_Blo[128*136];    // We1^T lo
__device__ __nv_bfloat16 g_W2hi[16*136];    // We2^T hi, padded [c][136]
__device__ __nv_bfloat16 g_W2lo[16*136];    // We2^T lo

__device__ __forceinline__ float lrelu(float v){ return v >= 0.f ? v : 0.1f*v; }

__device__ __forceinline__ uint32_t smem_u32(const void* p){
    uint32_t a;
    asm("{ .reg .u64 t; cvta.to.shared.u64 t, %1; cvt.u32.u64 %0, t; }"
        : "=r"(a) : "l"(p));
    return a;
}

#define LDM4(r, addr) \
    asm volatile("ldmatrix.sync.aligned.m8n8.x4.shared.b16 {%0,%1,%2,%3}, [%4];" \
        : "=r"((r)[0]), "=r"((r)[1]), "=r"((r)[2]), "=r"((r)[3]) : "r"(addr))

#define MMA16816(d, a, b0_, b1_) \
    asm volatile("mma.sync.aligned.m16n8k16.row.col.f32.bf16.bf16.f32 " \
        "{%0,%1,%2,%3}, {%4,%5,%6,%7}, {%8,%9}, {%0,%1,%2,%3};" \
        : "+f"((d)[0]), "+f"((d)[1]), "+f"((d)[2]), "+f"((d)[3]) \
        : "r"((a)[0]), "r"((a)[1]), "r"((a)[2]), "r"((a)[3]), "r"(b0_), "r"(b1_))

// ---------------------------------------------------------------------------
// K1: 3-layer GCN on complete graph (unchanged, passing).
// ---------------------------------------------------------------------------
__global__ void k1_gcn(const float* __restrict__ x,
                       const float* __restrict__ Wg0, const float* __restrict__ bg0,
                       const float* __restrict__ Wg1, const float* __restrict__ bg1,
                       const float* __restrict__ Wg2, const float* __restrict__ bg2,
                       float* __restrict__ h_out)
{
    __shared__ float buf[128*65];
    __shared__ float S[64];
    const int n = threadIdx.x;
    const int base = blockIdx.x * NN;
    const float inv = 1.0f/127.0f;

    float xr[D_IN];
#pragma unroll
    for (int k=0;k<D_IN;k++) xr[k] = x[(base+n)*D_IN + k];

    float y[64];
#pragma unroll
    for (int c=0;c<32;c++){
        float a = 0.f;
#pragma unroll
        for (int k=0;k<D_IN;k++) a += xr[k]*__ldg(&Wg0[k*32+c]);
        y[c]=a; buf[n*65+c]=a;
    }
    __syncthreads();
    if (n<32){ float s=0.f; for(int m=0;m<128;m++) s += buf[m*65+n]; S[n]=s; }
    __syncthreads();
#pragma unroll
    for (int c=0;c<32;c++) buf[n*65+c] = lrelu((S[c]-y[c])*inv + __ldg(&bg0[c]));
    __syncthreads();

#pragma unroll
    for (int c=0;c<32;c++){
        float a = 0.f;
#pragma unroll
        for (int k=0;k<32;k++) a += buf[n*65+k]*__ldg(&Wg1[k*32+c]);
        y[c]=a;
    }
    __syncthreads();
#pragma unroll
    for (int c=0;c<32;c++) buf[n*65+c]=y[c];
    __syncthreads();
    if (n<32){ float s=0.f; for(int m=0;m<128;m++) s += buf[m*65+n]; S[n]=s; }
    __syncthreads();
#pragma unroll
    for (int c=0;c<32;c++) buf[n*65+c] = lrelu((S[c]-y[c])*inv + __ldg(&bg1[c]));
    __syncthreads();

#pragma unroll
    for (int c=0;c<64;c++){
        float a = 0.f;
#pragma unroll
        for (int k=0;k<32;k++) a += buf[n*65+k]*__ldg(&Wg2[k*64+c]);
        y[c]=a;
    }
    __syncthreads();
#pragma unroll
    for (int c=0;c<64;c++) buf[n*65+c]=y[c];
    __syncthreads();
    if (n<64){ float s=0.f; for(int m=0;m<128;m++) s += buf[m*65+n]; S[n]=s; }
    __syncthreads();
#pragma unroll
    for (int c=0;c<64;c++)
        h_out[(base+n)*64 + c] = (S[c]-y[c])*inv + __ldg(&bg2[c]);
}

// ---------------------------------------------------------------------------
// K2: A0 = h @ We0[:64,:], B0 = h @ We0[64:,:]  (unchanged, passing)
// ---------------------------------------------------------------------------
__global__ void k2_ab(const float* __restrict__ h, const float* __restrict__ We0)
{
    __shared__ float hs[32*64];
    const int tid = threadIdx.x;
    const int n0 = blockIdx.x * 32;

    for (int l = tid; l < 32*64; l += 256) hs[l] = h[n0*64 + l];
    __syncthreads();

    const int col = tid & 127;
    const int kb  = (tid >> 7) * 64;

    float acc[32];
#pragma unroll
    for (int i=0;i<32;i++) acc[i]=0.f;

    for (int k=0;k<64;k++){
        float w = __ldg(&We0[(kb+k)*128 + col]);
#pragma unroll
        for (int nn=0;nn<32;nn++) acc[nn] += hs[nn*64+k]*w;
    }

    float* dst = (tid < 128) ? g_A0 : g_B0;
#pragma unroll
    for (int nn=0;nn<32;nn++) dst[(size_t)(n0+nn)*128 + col] = acc[nn];
}

// ---------------------------------------------------------------------------
// K2b: node MLP + diagonal 4x4 blocks of U (unchanged, passing)
// ---------------------------------------------------------------------------
__global__ void k2b_node(const float* __restrict__ h,
                         const float* __restrict__ Wn0, const float* __restrict__ bn0,
                         const float* __restrict__ Wn1, const float* __restrict__ bn1,
                         const float* __restrict__ Wn2, const float* __restrict__ bn2,
                         float* __restrict__ U)
{
    __shared__ float w0[64*64], w1[64*64], w2[64*10];
    __shared__ float b0s[64], b1s[64], b2s[10];
    const int n = threadIdx.x;
    const int b = blockIdx.x;

    for (int l=n; l<4096; l+=128){ w0[l]=Wn0[l]; w1[l]=Wn1[l]; }
    for (int l=n; l<640;  l+=128) w2[l]=Wn2[l];
    if (n<64){ b0s[n]=bn0[n]; b1s[n]=bn1[n]; }
    if (n<10) b2s[n]=bn2[n];
    __syncthreads();

    const float* hr = h + (size_t)(b*NN+n)*64;
    float h0[64];
#pragma unroll
    for (int k=0;k<64;k++) h0[k]=hr[k];

    float t1[64];
#pragma unroll
    for (int c=0;c<64;c++){
        float a=b0s[c];
#pragma unroll
        for (int k=0;k<64;k++) a += h0[k]*w0[k*64+c];
        t1[c]=lrelu(a);
    }
    float t2[64];
#pragma unroll
    for (int c=0;c<64;c++){
        float a=b1s[c];
#pragma unroll
        for (int k=0;k<64;k++) a += t1[k]*w1[k*64+c];
        t2[c]=lrelu(a);
    }
    float v[10];
#pragma unroll
    for (int c=0;c<10;c++){
        float a=b2s[c];
#pragma unroll
        for (int k=0;k<64;k++) a += t2[k]*w2[k*10+c];
        v[c]=a;
    }

    const int SMAT[16] = {0,1,2,3, 1,4,5,6, 2,5,7,8, 3,6,8,9};
    float* Ub = U + (size_t)b*U_PER_B;
#pragma unroll
    for (int a=0;a<4;a++){
        float4 r;
        r.x = v[SMAT[a*4+0]]; r.y = v[SMAT[a*4+1]];
        r.z = v[SMAT[a*4+2]]; r.w = v[SMAT[a*4+3]];
        *reinterpret_cast<float4*>(Ub + (size_t)(4*n+a)*U_STRIDE + 4*n) = r;
    }
}

// ---------------------------------------------------------------------------
// K_prep: split We1^T and We2^T into bf16 hi/lo padded layouts (once).
// ---------------------------------------------------------------------------
__global__ void k_prep(const float* __restrict__ We1, const float* __restrict__ We2)
{
    int idx = blockIdx.x*256 + threadIdx.x;
    if (idx < 128*128){
        int k = idx >> 7, n = idx & 127;
        float w = We1[k*128 + n];
        __nv_bfloat16 h = __float2bfloat16_rn(w);
        float lo = w - __bfloat162float(h);
        g_Bhi[n*136 + k] = h;
        g_Blo[n*136 + k] = __float2bfloat16_rn(lo);
    } else if (idx < 128*128 + 128*16){
        int r = idx - 128*128;
        int k = r >> 4, c = r & 15;
        float w = We2[k*16 + c];
        __nv_bfloat16 h = __float2bfloat16_rn(w);
        float lo = w - __bfloat162float(h);
        g_W2hi[c*136 + k] = h;
        g_W2lo[c*136 + k] = __float2bfloat16_rn(lo);
    }
}

// ---------------------------------------------------------------------------
// K3: edge MLP via mma.sync bf16 3-split. Tile = 128 pairs (8 i x 16 j).
// SMEM layout (bytes):
// ---------------------------------------------------------------------------
#define OFF_THI  0                    // t0hi / t1hi  bf16 [128][136] = 34816
#define OFF_TLO  34816                // t0lo / t1lo
#define OFF_BHI  69632                // We1T hi bf16 [128][136]
#define OFF_BLO  104448
#define OFF_W2HI 139264               // We2T hi bf16 [16][136] = 4352
#define OFF_W2LO 143616
#define OFF_BE1  147968               // 128 f
#define OFF_BE2  148480               // 16 f
#define OFF_ES   148544               // e staging 128*16 f = 8192
#define K3_SMEM  (OFF_ES + 8192)      // 156736 B

__global__ void __launch_bounds__(256, 1)
k3_edge_mma(const float* __restrict__ be0,
            const float* __restrict__ be1,
            const float* __restrict__ be2,
            float* __restrict__ U)
{
    extern __shared__ char smem[];
    float* smemf = reinterpret_cast<float*>(smem);
    const uint32_t sb = smem_u32(smem);
    const int tid = threadIdx.x;
    const int wid = tid >> 5;
    const int lane = tid & 31;

    // triangular tile decode: jt s.t. jt(jt+1) <= t < (jt+1)(jt+2)
    const int t = blockIdx.x;
    int jt = 0;
#pragma unroll
    for (int q=1;q<8;q++) if (t >= q*(q+1)) jt = q;
    const int it = t - jt*(jt+1);
    const int b  = blockIdx.y;
    const int i0 = it*8, j0 = jt*16;

    // ---- stage weights ----
    {
        const uint4* sh  = reinterpret_cast<const uint4*>(g_Bhi);
        const uint4* sl  = reinterpret_cast<const uint4*>(g_Blo);
        uint4* dh = reinterpret_cast<uint4*>(smem + OFF_BHI);
        uint4* dl = reinterpret_cast<uint4*>(smem + OFF_BLO);
        for (int l = tid; l < 2176; l += 256){ dh[l] = sh[l]; dl[l] = sl[l]; }
        const uint4* s2h = reinterpret_cast<const uint4*>(g_W2hi);
        const uint4* s2l = reinterpret_cast<const uint4*>(g_W2lo);
        uint4* d2h = reinterpret_cast<uint4*>(smem + OFF_W2HI);
        uint4* d2l = reinterpret_cast<uint4*>(smem + OFF_W2LO);
        if (tid < 256){
            if (tid < 272-16){} // no-op keep shape
        }
        for (int l = tid; l < 272; l += 256){ d2h[l] = s2h[l]; d2l[l] = s2l[l]; }
        if (tid < 128) smemf[OFF_BE1/4 + tid] = be1[tid];
        else if (tid < 144) smemf[OFF_BE2/4 + tid - 128] = be2[tid - 128];
    }

    // ---- build t0 = lrelu(A0[i] + B0[j] + be0), split bf16 hi/lo ----
    {
        const int p = tid >> 1, h = tid & 1;
        const float* Ar = g_A0 + ((size_t)(b*NN + i0 + (p>>4)))*128 + h*64;
        const float* Br = g_B0 + ((size_t)(b*NN + j0 + (p&15)))*128 + h*64;
        __nv_bfloat162* thi = reinterpret_cast<__nv_bfloat162*>(smem + OFF_THI);
        __nv_bfloat162* tlo = reinterpret_cast<__nv_bfloat162*>(smem + OFF_TLO);
        const int base2 = p*68 + h*32;
#pragma unroll
        for (int k4 = 0; k4 < 16; k4++){
            float4 a  = *reinterpret_cast<const float4*>(Ar + k4*4);
            float4 bb = *reinterpret_cast<const float4*>(Br + k4*4);
            float4 e0 = *reinterpret_cast<const float4*>(be0 + h*64 + k4*4);
            float s0 = lrelu(a.x + bb.x + e0.x);
            float s1 = lrelu(a.y + bb.y + e0.y);
            float s2 = lrelu(a.z + bb.z + e0.z);
            float s3 = lrelu(a.w + bb.w + e0.w);
            __nv_bfloat162 h01 = __floats2bfloat162_rn(s0, s1);
            __nv_bfloat162 h23 = __floats2bfloat162_rn(s2, s3);
            __nv_bfloat162 l01 = __floats2bfloat162_rn(s0 - __low2float(h01), s1 - __high2float(h01));
            __nv_bfloat162 l23 = __floats2bfloat162_rn(s2 - __low2float(h23), s3 - __high2float(h23));
            thi[base2 + k4*2]     = h01;
            thi[base2 + k4*2 + 1] = h23;
            tlo[base2 + k4*2]     = l01;
            tlo[base2 + k4*2 + 1] = l23;
        }
    }
    __syncthreads();

    // ---- GEMM1: t1 = t0 @ We1, warp tile 32x64, 3-split bf16 ----
    const int mg = wid >> 1;       // 0..3 -> rows mg*32..+31
    const int ng = wid & 1;        // 0..1 -> cols ng*64..+63
    float acc[2][8][4];
#pragma unroll
    for (int a1=0;a1<2;a1++)
#pragma unroll
        for (int a2=0;a2<8;a2++)
#pragma unroll
            for (int a3=0;a3<4;a3++) acc[a1][a2][a3] = 0.f;

    {
        const uint32_t aOff = (uint32_t)((mg*32 + (lane & 15))*272 + (lane >> 4)*16);
        const uint32_t bOff = (uint32_t)((ng*64 + ((lane >> 4) << 3) + (lane & 7))*272
                                        + ((lane >> 3) & 1)*16);
        const uint32_t aHi = sb + OFF_THI + aOff, aLo = sb + OFF_TLO + aOff;
        const uint32_t bHi = sb + OFF_BHI + bOff, bLo = sb + OFF_BLO + bOff;

#pragma unroll
        for (int ks = 0; ks < 8; ks++){
            uint32_t ah0[4], ah1[4], al0[4], al1[4];
            LDM4(ah0, aHi + ks*32);
            LDM4(ah1, aHi + 4352 + ks*32);
            LDM4(al0, aLo + ks*32);
            LDM4(al1, aLo + 4352 + ks*32);
#pragma unroll
            for (int n2 = 0; n2 < 4; n2++){
                uint32_t bh[4], bl[4];
                LDM4(bh, bHi + n2*4352 + ks*32);
                LDM4(bl, bLo + n2*4352 + ks*32);
                MMA16816(acc[0][2*n2],   ah0, bh[0], bh[1]);
                MMA16816(acc[0][2*n2],   al0, bh[0], bh[1]);
                MMA16816(acc[0][2*n2],   ah0, bl[0], bl[1]);
                MMA16816(acc[0][2*n2+1], ah0, bh[2], bh[3]);
                MMA16816(acc[0][2*n2+1], al0, bh[2], bh[3]);
                MMA16816(acc[0][2*n2+1], ah0, bl[2], bl[3]);
                MMA16816(acc[1][2*n2],   ah1, bh[0], bh[1]);
                MMA16816(acc[1][2*n2],   al1, bh[0], bh[1]);
                MMA16816(acc[1][2*n2],   ah1, bl[0], bl[1]);
                MMA16816(acc[1][2*n2+1], ah1, bh[2], bh[3]);
                MMA16816(acc[1][2*n2+1], al1, bh[2], bh[3]);
                MMA16816(acc[1][2*n2+1], ah1, bl[2], bl[3]);
            }
        }
    }
    __syncthreads();   // all t0 reads complete before overwrite

    // ---- t1 = lrelu(acc + be1), split bf16 hi/lo in place ----
    {
        const int g = lane >> 2, r = lane & 3;
        __nv_bfloat162* thi = reinterpret_cast<__nv_bfloat162*>(smem + OFF_THI);
        __nv_bfloat162* tlo = reinterpret_cast<__nv_bfloat162*>(smem + OFF_TLO);
#pragma unroll
        for (int mt = 0; mt < 2; mt++){
#pragma unroll
            for (int nt = 0; nt < 8; nt++){
                const int R0 = mg*32 + mt*16 + g;
                const int C  = ng*64 + nt*8 + 2*r;
                const float b0v = smemf[OFF_BE1/4 + C];
                const float b1v = smemf[OFF_BE1/4 + C + 1];
                float s0 = lrelu(acc[mt][nt][0] + b0v);
                float s1 = lrelu(acc[mt][nt][1] + b1v);
                float s2 = lrelu(acc[mt][nt][2] + b0v);
                float s3 = lrelu(acc[mt][nt][3] + b1v);
                __nv_bfloat162 h01 = __floats2bfloat162_rn(s0, s1);
                __nv_bfloat162 h23 = __floats2bfloat162_rn(s2, s3);
                __nv_bfloat162 l01 = __floats2bfloat162_rn(s0 - __low2float(h01), s1 - __high2float(h01));
                __nv_bfloat162 l23 = __floats2bfloat162_rn(s2 - __low2float(h23), s3 - __high2float(h23));
                const int w0 = R0*68 + (C >> 1);
                const int w1 = (R0 + 8)*68 + (C >> 1);
                thi[w0] = h01; tlo[w0] = l01;
                thi[w1] = h23; tlo[w1] = l23;
            }
        }
    }
    __syncthreads();

    // ---- GEMM2: e = t1 @ We2 (N=16), warp = 16 pairs, 3-split ----
    {
        float e[2][4];
#pragma unroll
        for (int a2=0;a2<2;a2++)
#pragma unroll
            for (int a3=0;a3<4;a3++) e[a2][a3] = 0.f;

        const uint32_t aOff = (uint32_t)((wid*16 + (lane & 15))*272 + (lane >> 4)*16);
        const uint32_t bOff = (uint32_t)((((lane >> 4) << 3) + (lane & 7))*272
                                        + ((lane >> 3) & 1)*16);
        const uint32_t aHi = sb + OFF_THI + aOff, aLo = sb + OFF_TLO + aOff;
        const uint32_t wHi = sb + OFF_W2HI + bOff, wLo = sb + OFF_W2LO + bOff;

#pragma unroll
        for (int ks = 0; ks < 8; ks++){
            uint32_t ah[4], al[4], bh[4], bl[4];
            LDM4(ah, aHi + ks*32);
            LDM4(al, aLo + ks*32);
            LDM4(bh, wHi + ks*32);
            LDM4(bl, wLo + ks*32);
            MMA16816(e[0], ah, bh[0], bh[1]);
            MMA16816(e[0], al, bh[0], bh[1]);
            MMA16816(e[0], ah, bl[0], bl[1]);
            MMA16816(e[1], ah, bh[2], bh[3]);
            MMA16816(e[1], al, bh[2], bh[3]);
            MMA16816(e[1], ah, bl[2], bl[3]);
        }

        // stage e to smem [128][16]
        const int g = lane >> 2, r = lane & 3;
        float* es = smemf + OFF_ES/4;
#pragma unroll
        for (int nt = 0; nt < 2; nt++){
            const int C = nt*8 + 2*r;
            const int P0 = wid*16 + g;
            *reinterpret_cast<float2*>(&es[P0*16 + C])     = make_float2(e[nt][0], e[nt][1]);
            *reinterpret_cast<float2*>(&es[(P0+8)*16 + C]) = make_float2(e[nt][2], e[nt][3]);
        }
    }
    __syncthreads();

    // ---- scatter into U ----
    {
        const int p = tid >> 1, side = tid & 1;
        const int i = i0 + (p >> 4);
        const int j = j0 + (p & 15);
        if (i < j){
            const float* es = smemf + OFF_ES/4 + p*16;
            float* Ub = U + (size_t)b*U_PER_B;
#pragma unroll
            for (int q = 0; q < 4; q++){
                float4 v4;
                v4.x = es[q*4+0] + smemf[OFF_BE2/4 + q*4+0];
                v4.y = es[q*4+1] + smemf[OFF_BE2/4 + q*4+1];
                v4.z = es[q*4+2] + smemf[OFF_BE2/4 + q*4+2];
                v4.w = es[q*4+3] + smemf[OFF_BE2/4 + q*4+3];
                if (side == 0)
                    *reinterpret_cast<float4*>(Ub + (size_t)(4*i+q)*U_STRIDE + 4*j) = v4;
                else
                    *reinterpret_cast<float4*>(Ub + (size_t)(4*j+q)*U_STRIDE + 4*i) = v4;
            }
        }
    }
}

// ---------------------------------------------------------------------------
extern "C" void kernel_launch(void* const* d_in, const int* in_sizes, int n_in,
                              void* d_out, int out_size)
{
    const float* x   = (const float*)d_in[0];
    const float* Wg0 = (const float*)d_in[4];
    const float* bg0 = (const float*)d_in[5];
    const float* Wg1 = (const float*)d_in[6];
    const float* bg1 = (const float*)d_in[7];
    const float* Wg2 = (const float*)d_in[8];
    const float* bg2 = (const float*)d_in[9];
    const float* Wn0 = (const float*)d_in[10];
    const float* bn0 = (const float*)d_in[11];
    const float* Wn1 = (const float*)d_in[12];
    const float* bn1 = (const float*)d_in[13];
    const float* Wn2 = (const float*)d_in[14];
    const float* bn2 = (const float*)d_in[15];
    const float* We0 = (const float*)d_in[16];
    const float* be0 = (const float*)d_in[17];
    const float* We1 = (const float*)d_in[18];
    const float* be1 = (const float*)d_in[19];
    const float* We2 = (const float*)d_in[20];
    const float* be2 = (const float*)d_in[21];

    float* h_out = (float*)d_out;                 // (16384, 64)
    float* U     = h_out + (size_t)TOTAL*D_MP;    // (128, 512, 512)

    static bool attr_set = false;
    if (!attr_set){
        cudaFuncSetAttribute(k3_edge_mma, cudaFuncAttributeMaxDynamicSharedMemorySize, K3_SMEM);
        attr_set = true;
    }

    k_prep<<<72, 256>>>(We1, We2);
    k1_gcn<<<BATCH, 128>>>(x, Wg0,bg0, Wg1,bg1, Wg2,bg2, h_out);
    k2_ab<<<TOTAL/32, 256>>>(h_out, We0);
    k2b_node<<<BATCH, 128>>>(h_out, Wn0,bn0, Wn1,bn1, Wn2,bn2, U);
    k3_edge_mma<<<dim3(72, BATCH), 256, K3_SMEM>>>(be0, be1, be2, U);
}

// round 5
// speedup vs baseline: 3.7855x; 1.8169x over previous
#include <cuda_runtime.h>
#include <cuda_bf16.h>
#include <cstdint>

// Problem constants
#define BATCH 128
#define NN    128
#define D_IN  6
#define D_MP  64
#define TOTAL (BATCH*NN)    // 16384
#define U_STRIDE 512
#define U_PER_B  (512*512)

__device__ float g_A0[TOTAL*128];           // h @ We0[:64]
__device__ float g_B0[TOTAL*128];           // h @ We0[64:]
__device__ __nv_bfloat16 g_Bhi[128*136];    // We1^T hi, padded [n][136]
__device__ __nv_bfloat16 g_Blo[128*136];    // We1^T lo
__device__ __nv_bfloat16 g_W2hi[16*136];    // We2^T hi, padded [c][136]
__device__ __nv_bfloat16 g_W2lo[16*136];    // We2^T lo

__device__ __forceinline__ float lrelu(float v){ return v >= 0.f ? v : 0.1f*v; }

__device__ __forceinline__ uint32_t smem_u32(const void* p){
    uint32_t a;
    asm("{ .reg .u64 t; cvta.to.shared.u64 t, %1; cvt.u32.u64 %0, t; }"
        : "=r"(a) : "l"(p));
    return a;
}

#define LDM4(r, addr) \
    asm volatile("ldmatrix.sync.aligned.m8n8.x4.shared.b16 {%0,%1,%2,%3}, [%4];" \
        : "=r"((r)[0]), "=r"((r)[1]), "=r"((r)[2]), "=r"((r)[3]) : "r"(addr))

#define MMA16816(d, a, b0_, b1_) \
    asm volatile("mma.sync.aligned.m16n8k16.row.col.f32.bf16.bf16.f32 " \
        "{%0,%1,%2,%3}, {%4,%5,%6,%7}, {%8,%9}, {%0,%1,%2,%3};" \
        : "+f"((d)[0]), "+f"((d)[1]), "+f"((d)[2]), "+f"((d)[3]) \
        : "r"((a)[0]), "r"((a)[1]), "r"((a)[2]), "r"((a)[3]), "r"(b0_), "r"(b1_))

__device__ __forceinline__ void split2(float s0, float s1, uint32_t& hi, uint32_t& lo){
    __nv_bfloat162 h2 = __floats2bfloat162_rn(s0, s1);
    __nv_bfloat162 l2 = __floats2bfloat162_rn(s0 - __low2float(h2), s1 - __high2float(h2));
    hi = *reinterpret_cast<uint32_t*>(&h2);
    lo = *reinterpret_cast<uint32_t*>(&l2);
}

// ---------------------------------------------------------------------------
// K1: 3-layer GCN on complete graph (unchanged, passing).
// ---------------------------------------------------------------------------
__global__ void k1_gcn(const float* __restrict__ x,
                       const float* __restrict__ Wg0, const float* __restrict__ bg0,
                       const float* __restrict__ Wg1, const float* __restrict__ bg1,
                       const float* __restrict__ Wg2, const float* __restrict__ bg2,
                       float* __restrict__ h_out)
{
    __shared__ float buf[128*65];
    __shared__ float S[64];
    const int n = threadIdx.x;
    const int base = blockIdx.x * NN;
    const float inv = 1.0f/127.0f;

    float xr[D_IN];
#pragma unroll
    for (int k=0;k<D_IN;k++) xr[k] = x[(base+n)*D_IN + k];

    float y[64];
#pragma unroll
    for (int c=0;c<32;c++){
        float a = 0.f;
#pragma unroll
        for (int k=0;k<D_IN;k++) a += xr[k]*__ldg(&Wg0[k*32+c]);
        y[c]=a; buf[n*65+c]=a;
    }
    __syncthreads();
    if (n<32){ float s=0.f; for(int m=0;m<128;m++) s += buf[m*65+n]; S[n]=s; }
    __syncthreads();
#pragma unroll
    for (int c=0;c<32;c++) buf[n*65+c] = lrelu((S[c]-y[c])*inv + __ldg(&bg0[c]));
    __syncthreads();

#pragma unroll
    for (int c=0;c<32;c++){
        float a = 0.f;
#pragma unroll
        for (int k=0;k<32;k++) a += buf[n*65+k]*__ldg(&Wg1[k*32+c]);
        y[c]=a;
    }
    __syncthreads();
#pragma unroll
    for (int c=0;c<32;c++) buf[n*65+c]=y[c];
    __syncthreads();
    if (n<32){ float s=0.f; for(int m=0;m<128;m++) s += buf[m*65+n]; S[n]=s; }
    __syncthreads();
#pragma unroll
    for (int c=0;c<32;c++) buf[n*65+c] = lrelu((S[c]-y[c])*inv + __ldg(&bg1[c]));
    __syncthreads();

#pragma unroll
    for (int c=0;c<64;c++){
        float a = 0.f;
#pragma unroll
        for (int k=0;k<32;k++) a += buf[n*65+k]*__ldg(&Wg2[k*64+c]);
        y[c]=a;
    }
    __syncthreads();
#pragma unroll
    for (int c=0;c<64;c++) buf[n*65+c]=y[c];
    __syncthreads();
    if (n<64){ float s=0.f; for(int m=0;m<128;m++) s += buf[m*65+n]; S[n]=s; }
    __syncthreads();
#pragma unroll
    for (int c=0;c<64;c++)
        h_out[(base+n)*64 + c] = (S[c]-y[c])*inv + __ldg(&bg2[c]);
}

// ---------------------------------------------------------------------------
// K2: A0 = h @ We0[:64,:], B0 = h @ We0[64:,:]  (unchanged, passing)
// ---------------------------------------------------------------------------
__global__ void k2_ab(const float* __restrict__ h, const float* __restrict__ We0)
{
    __shared__ float hs[32*64];
    const int tid = threadIdx.x;
    const int n0 = blockIdx.x * 32;

    for (int l = tid; l < 32*64; l += 256) hs[l] = h[n0*64 + l];
    __syncthreads();

    const int col = tid & 127;
    const int kb  = (tid >> 7) * 64;

    float acc[32];
#pragma unroll
    for (int i=0;i<32;i++) acc[i]=0.f;

    for (int k=0;k<64;k++){
        float w = __ldg(&We0[(kb+k)*128 + col]);
#pragma unroll
        for (int nn=0;nn<32;nn++) acc[nn] += hs[nn*64+k]*w;
    }

    float* dst = (tid < 128) ? g_A0 : g_B0;
#pragma unroll
    for (int nn=0;nn<32;nn++) dst[(size_t)(n0+nn)*128 + col] = acc[nn];
}

// ---------------------------------------------------------------------------
// K2b: node MLP + diagonal 4x4 blocks of U.
// 512 blocks x 128 threads; 32 nodes/block, 4 threads/node (16 cols each).
// Dynamic smem layout (floats):
//   w0 [64][16]f4 = 4096, w1 = 4096, w2 [64][12] = 768,
//   bufA [32][68] = 2176, bufB = 2176, vbuf [32][13] = 416,
//   b0 64, b1 64, b2 12
// ---------------------------------------------------------------------------
#define K2B_W0   0
#define K2B_W1   4096
#define K2B_W2   8192
#define K2B_BA   8960
#define K2B_BB   11136
#define K2B_VB   13312
#define K2B_B0   13728
#define K2B_B1   13792
#define K2B_B2   13856
#define K2B_SMEM ((13856+16)*4)

__global__ void __launch_bounds__(128)
k2b_node(const float* __restrict__ h,
         const float* __restrict__ Wn0, const float* __restrict__ bn0,
         const float* __restrict__ Wn1, const float* __restrict__ bn1,
         const float* __restrict__ Wn2, const float* __restrict__ bn2,
         float* __restrict__ U)
{
    extern __shared__ float sm[];
    const int tid = threadIdx.x;
    const int ln  = tid >> 2;
    const int q   = tid & 3;
    const int b   = blockIdx.x >> 2;
    const int n0  = (blockIdx.x & 3) * 32;

    float4* w0s = reinterpret_cast<float4*>(sm + K2B_W0);
    float4* w1s = reinterpret_cast<float4*>(sm + K2B_W1);

    for (int l = tid; l < 1024; l += 128){
        w0s[l] = reinterpret_cast<const float4*>(Wn0)[l];
        w1s[l] = reinterpret_cast<const float4*>(Wn1)[l];
    }
    for (int l = tid; l < 768; l += 128){
        int k = l / 12, c = l % 12;
        sm[K2B_W2 + l] = (c < 10) ? Wn2[k*10 + c] : 0.f;
    }
    if (tid < 64){ sm[K2B_B0 + tid] = bn0[tid]; sm[K2B_B1 + tid] = bn1[tid]; }
    if (tid < 12) sm[K2B_B2 + tid] = (tid < 10) ? bn2[tid] : 0.f;
    for (int l = tid; l < 2048; l += 128){
        int r_ = l >> 6, c = l & 63;
        sm[K2B_BA + r_*68 + c] = h[(size_t)(b*128 + n0 + r_)*64 + c];
    }
    __syncthreads();

    // layer 1: bufA -> bufB
    {
        float acc[16];
#pragma unroll
        for (int m=0;m<16;m++) acc[m] = sm[K2B_B0 + q*16 + m];
        for (int k=0;k<64;k++){
            float hk = sm[K2B_BA + ln*68 + k];
#pragma unroll
            for (int c4=0;c4<4;c4++){
                float4 w = w0s[k*16 + q*4 + c4];
                acc[c4*4+0] += hk*w.x; acc[c4*4+1] += hk*w.y;
                acc[c4*4+2] += hk*w.z; acc[c4*4+3] += hk*w.w;
            }
        }
#pragma unroll
        for (int m=0;m<16;m++) sm[K2B_BB + ln*68 + q*16 + m] = lrelu(acc[m]);
    }
    __syncthreads();

    // layer 2: bufB -> bufA
    {
        float acc[16];
#pragma unroll
        for (int m=0;m<16;m++) acc[m] = sm[K2B_B1 + q*16 + m];
        for (int k=0;k<64;k++){
            float hk = sm[K2B_BB + ln*68 + k];
#pragma unroll
            for (int c4=0;c4<4;c4++){
                float4 w = w1s[k*16 + q*4 + c4];
                acc[c4*4+0] += hk*w.x; acc[c4*4+1] += hk*w.y;
                acc[c4*4+2] += hk*w.z; acc[c4*4+3] += hk*w.w;
            }
        }
        __syncthreads();
#pragma unroll
        for (int m=0;m<16;m++) sm[K2B_BA + ln*68 + q*16 + m] = lrelu(acc[m]);
    }
    __syncthreads();

    // layer 3: bufA -> vbuf (cols q, q+4, q+8)
    {
        float a0 = sm[K2B_B2 + q];
        float a1 = sm[K2B_B2 + q + 4];
        float a2 = sm[K2B_B2 + q + 8];
        for (int k=0;k<64;k++){
            float hk = sm[K2B_BA + ln*68 + k];
            a0 += hk * sm[K2B_W2 + k*12 + q];
            a1 += hk * sm[K2B_W2 + k*12 + q + 4];
            a2 += hk * sm[K2B_W2 + k*12 + q + 8];
        }
        sm[K2B_VB + ln*13 + q]     = a0;
        sm[K2B_VB + ln*13 + q + 4] = a1;
        sm[K2B_VB + ln*13 + q + 8] = a2;
    }
    __syncthreads();

    // diagonal write: thread q = row of the 4x4 block
    {
        const int SMAT[16] = {0,1,2,3, 1,4,5,6, 2,5,7,8, 3,6,8,9};
        const int node = n0 + ln;
        float4 rv;
        rv.x = sm[K2B_VB + ln*13 + SMAT[q*4+0]];
        rv.y = sm[K2B_VB + ln*13 + SMAT[q*4+1]];
        rv.z = sm[K2B_VB + ln*13 + SMAT[q*4+2]];
        rv.w = sm[K2B_VB + ln*13 + SMAT[q*4+3]];
        float* Ub = U + (size_t)b*U_PER_B;
        *reinterpret_cast<float4*>(Ub + (size_t)(4*node+q)*U_STRIDE + 4*node) = rv;
    }
}

// ---------------------------------------------------------------------------
// K_prep: split We1^T and We2^T into bf16 hi/lo padded layouts (once).
// ---------------------------------------------------------------------------
__global__ void k_prep(const float* __restrict__ We1, const float* __restrict__ We2)
{
    int idx = blockIdx.x*256 + threadIdx.x;
    if (idx < 128*128){
        int k = idx >> 7, n = idx & 127;
        float w = We1[k*128 + n];
        __nv_bfloat16 h = __float2bfloat16_rn(w);
        float lo = w - __bfloat162float(h);
        g_Bhi[n*136 + k] = h;
        g_Blo[n*136 + k] = __float2bfloat16_rn(lo);
    } else if (idx < 128*128 + 128*16){
        int r = idx - 128*128;
        int k = r >> 4, c = r & 15;
        float w = We2[k*16 + c];
        __nv_bfloat16 h = __float2bfloat16_rn(w);
        float lo = w - __bfloat162float(h);
        g_W2hi[c*136 + k] = h;
        g_W2lo[c*136 + k] = __float2bfloat16_rn(lo);
    }
}

// ---------------------------------------------------------------------------
// K3: edge MLP via mma.sync bf16 3-split, register-resident A + chained GEMM2.
// Tile = 128 pairs (8 i x 16 j), 8 warps (4 m-groups x 2 n-halves).
// ---------------------------------------------------------------------------
#define OFF_BHI  0                    // 34816
#define OFF_BLO  34816                // 34816
#define OFF_W2HI 69632                // 4352
#define OFF_W2LO 73984                // 4352
#define OFF_BE1  78336                // 512
#define OFF_BE2  78848                // 64
#define OFF_STG  78912                // A0s[8][132] + B0s[16][132] = 12672
#define OFF_A0S  OFF_STG
#define OFF_B0S  (OFF_STG + 8*132*4)
#define OFF_ES   OFF_STG              // alias: [128][20] f = 10240
#define K3_SMEM  (OFF_STG + 12672)    // 91584 B -> 2 CTAs/SM

__global__ void __launch_bounds__(256, 2)
k3_edge_mma(const float* __restrict__ be0,
            const float* __restrict__ be1,
            const float* __restrict__ be2,
            float* __restrict__ U)
{
    extern __shared__ char smem[];
    float* smemf = reinterpret_cast<float*>(smem);
    const uint32_t sb = smem_u32(smem);
    const int tid = threadIdx.x;
    const int wid = tid >> 5;
    const int lane = tid & 31;
    const int g = lane >> 2;
    const int r = lane & 3;

    // triangular tile decode: jt s.t. jt(jt+1) <= t < (jt+1)(jt+2)
    const int t = blockIdx.x;
    int jt = 0;
#pragma unroll
    for (int q=1;q<8;q++) if (t >= q*(q+1)) jt = q;
    const int it = t - jt*(jt+1);
    const int b  = blockIdx.y;
    const int i0 = it*8, j0 = jt*16;

    // ---- stage weights + A0/B0 rows ----
    {
        const uint4* sh  = reinterpret_cast<const uint4*>(g_Bhi);
        const uint4* sl  = reinterpret_cast<const uint4*>(g_Blo);
        uint4* dh = reinterpret_cast<uint4*>(smem + OFF_BHI);
        uint4* dl = reinterpret_cast<uint4*>(smem + OFF_BLO);
        for (int l = tid; l < 2176; l += 256){ dh[l] = sh[l]; dl[l] = sl[l]; }
        const uint4* s2h = reinterpret_cast<const uint4*>(g_W2hi);
        const uint4* s2l = reinterpret_cast<const uint4*>(g_W2lo);
        uint4* d2h = reinterpret_cast<uint4*>(smem + OFF_W2HI);
        uint4* d2l = reinterpret_cast<uint4*>(smem + OFF_W2LO);
        for (int l = tid; l < 272; l += 256){ d2h[l] = s2h[l]; d2l[l] = s2l[l]; }
        if (tid < 128) smemf[OFF_BE1/4 + tid] = be1[tid];
        else if (tid < 144) smemf[OFF_BE2/4 + tid - 128] = be2[tid - 128];
        // A0s: 8 rows x 128 f (no be0); B0s: 16 rows x 128 f (+be0)
        for (int l = tid; l < 256; l += 256){
            int rr = l >> 5, c4 = (l & 31)*4;
            float4 v = *reinterpret_cast<const float4*>(g_A0 + ((size_t)(b*NN + i0 + rr))*128 + c4);
            *reinterpret_cast<float4*>(smemf + OFF_A0S/4 + rr*132 + c4) = v;
        }
        for (int l = tid; l < 512; l += 256){
            int rr = l >> 5, c4 = (l & 31)*4;
            float4 v  = *reinterpret_cast<const float4*>(g_B0 + ((size_t)(b*NN + j0 + rr))*128 + c4);
            float4 e0 = *reinterpret_cast<const float4*>(be0 + c4);
            v.x += e0.x; v.y += e0.y; v.z += e0.z; v.w += e0.w;
            *reinterpret_cast<float4*>(smemf + OFF_B0S/4 + rr*132 + c4) = v;
        }
    }
    __syncthreads();

    const int mg = wid >> 1;       // 0..3 -> rows mg*32..+31
    const int ng = wid & 1;        // 0..1 -> cols ng*64..+63
    float acc[2][8][4];
#pragma unroll
    for (int a1=0;a1<2;a1++)
#pragma unroll
        for (int a2=0;a2<8;a2++)
#pragma unroll
            for (int a3=0;a3<4;a3++) acc[a1][a2][a3] = 0.f;

    // ---- GEMM1: register-built A (t0), ldmatrix B (We1^T hi/lo) ----
    {
        const uint32_t bOff = (uint32_t)((ng*64 + ((lane >> 4) << 3) + (lane & 7))*272
                                        + ((lane >> 3) & 1)*16);
        const uint32_t bHi = sb + OFF_BHI + bOff, bLo = sb + OFF_BLO + bOff;
        const float* A0p = smemf + OFF_A0S/4;
        const float* B0p = smemf + OFF_B0S/4;

#pragma unroll
        for (int ks = 0; ks < 8; ks++){
            // B0 rows j = g, g+8 (shared across mt)
            float2 b00 = *reinterpret_cast<const float2*>(B0p + g*132      + ks*16 + 2*r);
            float2 b01 = *reinterpret_cast<const float2*>(B0p + g*132      + ks*16 + 8 + 2*r);
            float2 b10 = *reinterpret_cast<const float2*>(B0p + (g+8)*132  + ks*16 + 2*r);
            float2 b11 = *reinterpret_cast<const float2*>(B0p + (g+8)*132  + ks*16 + 8 + 2*r);

            uint32_t ah[2][4], al[2][4];
#pragma unroll
            for (int mt=0; mt<2; mt++){
                const float* Ar = A0p + (mg*2+mt)*132 + ks*16;
                float2 ak0 = *reinterpret_cast<const float2*>(Ar + 2*r);
                float2 ak1 = *reinterpret_cast<const float2*>(Ar + 8 + 2*r);
                split2(lrelu(ak0.x+b00.x), lrelu(ak0.y+b00.y), ah[mt][0], al[mt][0]);
                split2(lrelu(ak0.x+b10.x), lrelu(ak0.y+b10.y), ah[mt][1], al[mt][1]);
                split2(lrelu(ak1.x+b01.x), lrelu(ak1.y+b01.y), ah[mt][2], al[mt][2]);
                split2(lrelu(ak1.x+b11.x), lrelu(ak1.y+b11.y), ah[mt][3], al[mt][3]);
            }
#pragma unroll
            for (int n2 = 0; n2 < 4; n2++){
                uint32_t bh[4], bl[4];
                LDM4(bh, bHi + n2*4352 + ks*32);
                LDM4(bl, bLo + n2*4352 + ks*32);
                MMA16816(acc[0][2*n2],   ah[0], bh[0], bh[1]);
                MMA16816(acc[0][2*n2],   al[0], bh[0], bh[1]);
                MMA16816(acc[0][2*n2],   ah[0], bl[0], bl[1]);
                MMA16816(acc[0][2*n2+1], ah[0], bh[2], bh[3]);
                MMA16816(acc[0][2*n2+1], al[0], bh[2], bh[3]);
                MMA16816(acc[0][2*n2+1], ah[0], bl[2], bl[3]);
                MMA16816(acc[1][2*n2],   ah[1], bh[0], bh[1]);
                MMA16816(acc[1][2*n2],   al[1], bh[0], bh[1]);
                MMA16816(acc[1][2*n2],   ah[1], bl[0], bl[1]);
                MMA16816(acc[1][2*n2+1], ah[1], bh[2], bh[3]);
                MMA16816(acc[1][2*n2+1], al[1], bh[2], bh[3]);
                MMA16816(acc[1][2*n2+1], ah[1], bl[2], bl[3]);
            }
        }
    }

    // ---- GEMM2: chain acc -> t1 A-fragments, partial e over warp's 64 cols ----
    float e[2][2][4];
#pragma unroll
    for (int a1=0;a1<2;a1++)
#pragma unroll
        for (int a2=0;a2<2;a2++)
#pragma unroll
            for (int a3=0;a3<4;a3++) e[a1][a2][a3] = 0.f;

    {
        const uint32_t b2Off = (uint32_t)(((((lane >> 4) << 3) + (lane & 7))*272)
                                        + ((lane >> 3) & 1)*16);
        const uint32_t wHi = sb + OFF_W2HI + b2Off, wLo = sb + OFF_W2LO + b2Off;

#pragma unroll
        for (int qk = 0; qk < 4; qk++){
            uint32_t bh[4], bl[4];
            LDM4(bh, wHi + (ng*4+qk)*32);
            LDM4(bl, wLo + (ng*4+qk)*32);
#pragma unroll
            for (int mt = 0; mt < 2; mt++){
                // A-tile: rows mg*32+mt*16+{g,g+8}, k = cols of C tiles nt=2qk,2qk+1
                const int ntA = 2*qk, ntB = 2*qk+1;
                const int cA = ng*64 + ntA*8 + 2*r;
                const int cB = ng*64 + ntB*8 + 2*r;
                float beA0 = smemf[OFF_BE1/4 + cA], beA1 = smemf[OFF_BE1/4 + cA + 1];
                float beB0 = smemf[OFF_BE1/4 + cB], beB1 = smemf[OFF_BE1/4 + cB + 1];
                uint32_t ah[4], al[4];
                split2(lrelu(acc[mt][ntA][0]+beA0), lrelu(acc[mt][ntA][1]+beA1), ah[0], al[0]);
                split2(lrelu(acc[mt][ntA][2]+beA0), lrelu(acc[mt][ntA][3]+beA1), ah[1], al[1]);
                split2(lrelu(acc[mt][ntB][0]+beB0), lrelu(acc[mt][ntB][1]+beB1), ah[2], al[2]);
                split2(lrelu(acc[mt][ntB][2]+beB0), lrelu(acc[mt][ntB][3]+beB1), ah[3], al[3]);
                MMA16816(e[mt][0], ah, bh[0], bh[1]);
                MMA16816(e[mt][0], al, bh[0], bh[1]);
                MMA16816(e[mt][0], ah, bl[0], bl[1]);
                MMA16816(e[mt][1], ah, bh[2], bh[3]);
                MMA16816(e[mt][1], al, bh[2], bh[3]);
                MMA16816(e[mt][1], ah, bl[2], bl[3]);
            }
        }
    }

    // ---- cross-warp (ng pair) reduction + scatter into U ----
    __syncthreads();   // A0s/B0s reads done; safe to overwrite with ES
    float* es = smemf + OFF_ES/4;   // [128][20]

    if (ng == 1){
#pragma unroll
        for (int mt=0; mt<2; mt++)
#pragma unroll
        for (int t_=0; t_<2; t_++)
#pragma unroll
        for (int rh=0; rh<2; rh++){
            int row = mg*32 + mt*16 + g + rh*8;
            int c = t_*8 + 2*r;
            *reinterpret_cast<float2*>(&es[row*20 + c]) =
                make_float2(e[mt][t_][rh*2+0], e[mt][t_][rh*2+1]);
        }
    }
    __syncthreads();
    if (ng == 0){
        float* Ub = U + (size_t)b*U_PER_B;
#pragma unroll
        for (int mt=0; mt<2; mt++)
#pragma unroll
        for (int t_=0; t_<2; t_++)
#pragma unroll
        for (int rh=0; rh<2; rh++){
            int row = mg*32 + mt*16 + g + rh*8;
            int c = t_*8 + 2*r;
            float2 part = *reinterpret_cast<const float2*>(&es[row*20 + c]);
            float vx = e[mt][t_][rh*2+0] + part.x + smemf[OFF_BE2/4 + c];
            float vy = e[mt][t_][rh*2+1] + part.y + smemf[OFF_BE2/4 + c + 1];
            int i = i0 + (row >> 4);
            int j = j0 + (row & 15);
            if (i < j){
                int qq = c >> 2, m = c & 3;
                float2 v2 = make_float2(vx, vy);
                *reinterpret_cast<float2*>(Ub + (size_t)(4*i+qq)*U_STRIDE + 4*j + m) = v2;
                *reinterpret_cast<float2*>(Ub + (size_t)(4*j+qq)*U_STRIDE + 4*i + m) = v2;
            }
        }
    }
}

// ---------------------------------------------------------------------------
extern "C" void kernel_launch(void* const* d_in, const int* in_sizes, int n_in,
                              void* d_out, int out_size)
{
    const float* x   = (const float*)d_in[0];
    const float* Wg0 = (const float*)d_in[4];
    const float* bg0 = (const float*)d_in[5];
    const float* Wg1 = (const float*)d_in[6];
    const float* bg1 = (const float*)d_in[7];
    const float* Wg2 = (const float*)d_in[8];
    const float* bg2 = (const float*)d_in[9];
    const float* Wn0 = (const float*)d_in[10];
    const float* bn0 = (const float*)d_in[11];
    const float* Wn1 = (const float*)d_in[12];
    const float* bn1 = (const float*)d_in[13];
    const float* Wn2 = (const float*)d_in[14];
    const float* bn2 = (const float*)d_in[15];
    const float* We0 = (const float*)d_in[16];
    const float* be0 = (const float*)d_in[17];
    const float* We1 = (const float*)d_in[18];
    const float* be1 = (const float*)d_in[19];
    const float* We2 = (const float*)d_in[20];
    const float* be2 = (const float*)d_in[21];

    float* h_out = (float*)d_out;                 // (16384, 64)
    float* U     = h_out + (size_t)TOTAL*D_MP;    // (128, 512, 512)

    static bool attr_set = false;
    if (!attr_set){
        cudaFuncSetAttribute(k3_edge_mma, cudaFuncAttributeMaxDynamicSharedMemorySize, K3_SMEM);
        cudaFuncSetAttribute(k2b_node, cudaFuncAttributeMaxDynamicSharedMemorySize, K2B_SMEM);
        attr_set = true;
    }

    k_prep<<<72, 256>>>(We1, We2);
    k1_gcn<<<BATCH, 128>>>(x, Wg0,bg0, Wg1,bg1, Wg2,bg2, h_out);
    k2_ab<<<TOTAL/32, 256>>>(h_out, We0);
    k2b_node<<<512, 128, K2B_SMEM>>>(h_out, Wn0,bn0, Wn1,bn1, Wn2,bn2, U);
    k3_edge_mma<<<dim3(72, BATCH), 256, K3_SMEM>>>(be0, be1, be2, U);
}

// round 6
// speedup vs baseline: 3.9996x; 1.0566x over previous
#include <cuda_runtime.h>
#include <cuda_bf16.h>
#include <cuda_fp16.h>
#include <cstdint>

// Problem constants
#define BATCH 128
#define NN    128
#define D_IN  6
#define D_MP  64
#define TOTAL (BATCH*NN)    // 16384
#define U_STRIDE 512
#define U_PER_B  (512*512)

__device__ float g_A0[TOTAL*128];           // h @ We0[:64]
__device__ float g_B0[TOTAL*128];           // h @ We0[64:]
__device__ __half g_Bhi[128*136];           // We1^T hi (fp16), padded [n][136]
__device__ __half g_Blo[128*136];           // We1^T lo (fp16 residual)
__device__ __nv_bfloat16 g_W2hi[16*136];    // We2^T hi, padded [c][136]
__device__ __nv_bfloat16 g_W2lo[16*136];    // We2^T lo

__device__ __forceinline__ float lrelu(float v){ return v >= 0.f ? v : 0.1f*v; }

__device__ __forceinline__ uint32_t smem_u32(const void* p){
    uint32_t a;
    asm("{ .reg .u64 t; cvta.to.shared.u64 t, %1; cvt.u32.u64 %0, t; }"
        : "=r"(a) : "l"(p));
    return a;
}

#define LDM4(r, addr) \
    asm volatile("ldmatrix.sync.aligned.m8n8.x4.shared.b16 {%0,%1,%2,%3}, [%4];" \
        : "=r"((r)[0]), "=r"((r)[1]), "=r"((r)[2]), "=r"((r)[3]) : "r"(addr))

#define MMA16816(d, a, b0_, b1_) \
    asm volatile("mma.sync.aligned.m16n8k16.row.col.f32.bf16.bf16.f32 " \
        "{%0,%1,%2,%3}, {%4,%5,%6,%7}, {%8,%9}, {%0,%1,%2,%3};" \
        : "+f"((d)[0]), "+f"((d)[1]), "+f"((d)[2]), "+f"((d)[3]) \
        : "r"((a)[0]), "r"((a)[1]), "r"((a)[2]), "r"((a)[3]), "r"(b0_), "r"(b1_))

#define MMA16816H(d, a, b0_, b1_) \
    asm volatile("mma.sync.aligned.m16n8k16.row.col.f32.f16.f16.f32 " \
        "{%0,%1,%2,%3}, {%4,%5,%6,%7}, {%8,%9}, {%0,%1,%2,%3};" \
        : "+f"((d)[0]), "+f"((d)[1]), "+f"((d)[2]), "+f"((d)[3]) \
        : "r"((a)[0]), "r"((a)[1]), "r"((a)[2]), "r"((a)[3]), "r"(b0_), "r"(b1_))

__device__ __forceinline__ void split2(float s0, float s1, uint32_t& hi, uint32_t& lo){
    __nv_bfloat162 h2 = __floats2bfloat162_rn(s0, s1);
    __nv_bfloat162 l2 = __floats2bfloat162_rn(s0 - __low2float(h2), s1 - __high2float(h2));
    hi = *reinterpret_cast<uint32_t*>(&h2);
    lo = *reinterpret_cast<uint32_t*>(&l2);
}
__device__ __forceinline__ uint32_t packh2(float s0, float s1){
    __half2 h2 = __floats2half2_rn(s0, s1);
    return *reinterpret_cast<uint32_t*>(&h2);
}

// ---------------------------------------------------------------------------
// K1: 3-layer GCN on complete graph (unchanged, passing).
// ---------------------------------------------------------------------------
__global__ void k1_gcn(const float* __restrict__ x,
                       const float* __restrict__ Wg0, const float* __restrict__ bg0,
                       const float* __restrict__ Wg1, const float* __restrict__ bg1,
                       const float* __restrict__ Wg2, const float* __restrict__ bg2,
                       float* __restrict__ h_out)
{
    __shared__ float buf[128*65];
    __shared__ float S[64];
    const int n = threadIdx.x;
    const int base = blockIdx.x * NN;
    const float inv = 1.0f/127.0f;

    float xr[D_IN];
#pragma unroll
    for (int k=0;k<D_IN;k++) xr[k] = x[(base+n)*D_IN + k];

    float y[64];
#pragma unroll
    for (int c=0;c<32;c++){
        float a = 0.f;
#pragma unroll
        for (int k=0;k<D_IN;k++) a += xr[k]*__ldg(&Wg0[k*32+c]);
        y[c]=a; buf[n*65+c]=a;
    }
    __syncthreads();
    if (n<32){ float s=0.f; for(int m=0;m<128;m++) s += buf[m*65+n]; S[n]=s; }
    __syncthreads();
#pragma unroll
    for (int c=0;c<32;c++) buf[n*65+c] = lrelu((S[c]-y[c])*inv + __ldg(&bg0[c]));
    __syncthreads();

#pragma unroll
    for (int c=0;c<32;c++){
        float a = 0.f;
#pragma unroll
        for (int k=0;k<32;k++) a += buf[n*65+k]*__ldg(&Wg1[k*32+c]);
        y[c]=a;
    }
    __syncthreads();
#pragma unroll
    for (int c=0;c<32;c++) buf[n*65+c]=y[c];
    __syncthreads();
    if (n<32){ float s=0.f; for(int m=0;m<128;m++) s += buf[m*65+n]; S[n]=s; }
    __syncthreads();
#pragma unroll
    for (int c=0;c<32;c++) buf[n*65+c] = lrelu((S[c]-y[c])*inv + __ldg(&bg1[c]));
    __syncthreads();

#pragma unroll
    for (int c=0;c<64;c++){
        float a = 0.f;
#pragma unroll
        for (int k=0;k<32;k++) a += buf[n*65+k]*__ldg(&Wg2[k*64+c]);
        y[c]=a;
    }
    __syncthreads();
#pragma unroll
    for (int c=0;c<64;c++) buf[n*65+c]=y[c];
    __syncthreads();
    if (n<64){ float s=0.f; for(int m=0;m<128;m++) s += buf[m*65+n]; S[n]=s; }
    __syncthreads();
#pragma unroll
    for (int c=0;c<64;c++)
        h_out[(base+n)*64 + c] = (S[c]-y[c])*inv + __ldg(&bg2[c]);
}

// ---------------------------------------------------------------------------
// K2: A0 = h @ We0[:64,:], B0 = h @ We0[64:,:]  (unchanged, passing)
// ---------------------------------------------------------------------------
__global__ void k2_ab(const float* __restrict__ h, const float* __restrict__ We0)
{
    __shared__ float hs[32*64];
    const int tid = threadIdx.x;
    const int n0 = blockIdx.x * 32;

    for (int l = tid; l < 32*64; l += 256) hs[l] = h[n0*64 + l];
    __syncthreads();

    const int col = tid & 127;
    const int kb  = (tid >> 7) * 64;

    float acc[32];
#pragma unroll
    for (int i=0;i<32;i++) acc[i]=0.f;

    for (int k=0;k<64;k++){
        float w = __ldg(&We0[(kb+k)*128 + col]);
#pragma unroll
        for (int nn=0;nn<32;nn++) acc[nn] += hs[nn*64+k]*w;
    }

    float* dst = (tid < 128) ? g_A0 : g_B0;
#pragma unroll
    for (int nn=0;nn<32;nn++) dst[(size_t)(n0+nn)*128 + col] = acc[nn];
}

// ---------------------------------------------------------------------------
// K2b: node MLP + diagonal 4x4 blocks of U.
// 512 blocks x 256 threads; 32 nodes/block, 8 threads/node (8 cols each).
// ---------------------------------------------------------------------------
#define K2B_W0   0
#define K2B_W1   4096
#define K2B_W2   8192
#define K2B_BA   8960
#define K2B_BB   11136
#define K2B_VB   13312
#define K2B_B0   13728
#define K2B_B1   13792
#define K2B_B2   13856
#define K2B_SMEM ((13856+16)*4)

__global__ void __launch_bounds__(256)
k2b_node(const float* __restrict__ h,
         const float* __restrict__ Wn0, const float* __restrict__ bn0,
         const float* __restrict__ Wn1, const float* __restrict__ bn1,
         const float* __restrict__ Wn2, const float* __restrict__ bn2,
         float* __restrict__ U)
{
    extern __shared__ float sm[];
    const int tid = threadIdx.x;
    const int ln  = tid >> 3;       // node 0..31
    const int q   = tid & 7;        // col group (8 cols)
    const int b   = blockIdx.x >> 2;
    const int n0  = (blockIdx.x & 3) * 32;

    float4* w0s = reinterpret_cast<float4*>(sm + K2B_W0);
    float4* w1s = reinterpret_cast<float4*>(sm + K2B_W1);

    for (int l = tid; l < 1024; l += 256){
        w0s[l] = reinterpret_cast<const float4*>(Wn0)[l];
        w1s[l] = reinterpret_cast<const float4*>(Wn1)[l];
    }
    for (int l = tid; l < 768; l += 256){
        int k = l / 12, c = l % 12;
        sm[K2B_W2 + l] = (c < 10) ? Wn2[k*10 + c] : 0.f;
    }
    if (tid < 64){ sm[K2B_B0 + tid] = bn0[tid]; sm[K2B_B1 + tid] = bn1[tid]; }
    else if (tid < 76) sm[K2B_B2 + tid - 64] = (tid - 64 < 10) ? bn2[tid-64] : 0.f;
    for (int l = tid; l < 2048; l += 256){
        int r_ = l >> 6, c = l & 63;
        sm[K2B_BA + r_*68 + c] = h[(size_t)(b*128 + n0 + r_)*64 + c];
    }
    __syncthreads();

    // layer 1: bufA -> bufB (cols q*8..q*8+7)
    {
        float acc[8];
#pragma unroll
        for (int m=0;m<8;m++) acc[m] = sm[K2B_B0 + q*8 + m];
        for (int k=0;k<64;k++){
            float hk = sm[K2B_BA + ln*68 + k];
            float4 wa = w0s[k*16 + q*2];
            float4 wb = w0s[k*16 + q*2 + 1];
            acc[0] += hk*wa.x; acc[1] += hk*wa.y; acc[2] += hk*wa.z; acc[3] += hk*wa.w;
            acc[4] += hk*wb.x; acc[5] += hk*wb.y; acc[6] += hk*wb.z; acc[7] += hk*wb.w;
        }
#pragma unroll
        for (int m=0;m<8;m++) sm[K2B_BB + ln*68 + q*8 + m] = lrelu(acc[m]);
    }
    __syncthreads();

    // layer 2: bufB -> bufA
    {
        float acc[8];
#pragma unroll
        for (int m=0;m<8;m++) acc[m] = sm[K2B_B1 + q*8 + m];
        for (int k=0;k<64;k++){
            float hk = sm[K2B_BB + ln*68 + k];
            float4 wa = w1s[k*16 + q*2];
            float4 wb = w1s[k*16 + q*2 + 1];
            acc[0] += hk*wa.x; acc[1] += hk*wa.y; acc[2] += hk*wa.z; acc[3] += hk*wa.w;
            acc[4] += hk*wb.x; acc[5] += hk*wb.y; acc[6] += hk*wb.z; acc[7] += hk*wb.w;
        }
        __syncthreads();
#pragma unroll
        for (int m=0;m<8;m++) sm[K2B_BA + ln*68 + q*8 + m] = lrelu(acc[m]);
    }
    __syncthreads();

    // layer 3: bufA -> vbuf (threads q<6 do 2 cols each)
    if (q < 6){
        const int c0 = 2*q, c1 = 2*q + 1;
        float a0 = sm[K2B_B2 + c0];
        float a1 = sm[K2B_B2 + c1];
        for (int k=0;k<64;k++){
            float hk = sm[K2B_BA + ln*68 + k];
            a0 += hk * sm[K2B_W2 + k*12 + c0];
            a1 += hk * sm[K2B_W2 + k*12 + c1];
        }
        sm[K2B_VB + ln*13 + c0] = a0;
        sm[K2B_VB + ln*13 + c1] = a1;
    }
    __syncthreads();

    // diagonal write: threads q<4, row q of the 4x4 block
    if (q < 4){
        const int SMAT[16] = {0,1,2,3, 1,4,5,6, 2,5,7,8, 3,6,8,9};
        const int node = n0 + ln;
        float4 rv;
        rv.x = sm[K2B_VB + ln*13 + SMAT[q*4+0]];
        rv.y = sm[K2B_VB + ln*13 + SMAT[q*4+1]];
        rv.z = sm[K2B_VB + ln*13 + SMAT[q*4+2]];
        rv.w = sm[K2B_VB + ln*13 + SMAT[q*4+3]];
        float* Ub = U + (size_t)b*U_PER_B;
        *reinterpret_cast<float4*>(Ub + (size_t)(4*node+q)*U_STRIDE + 4*node) = rv;
    }
}

// ---------------------------------------------------------------------------
// K_prep: We1^T -> fp16 hi/lo, We2^T -> bf16 hi/lo (once).
// ---------------------------------------------------------------------------
__global__ void k_prep(const float* __restrict__ We1, const float* __restrict__ We2)
{
    int idx = blockIdx.x*256 + threadIdx.x;
    if (idx < 128*128){
        int k = idx >> 7, n = idx & 127;
        float w = We1[k*128 + n];
        __half h = __float2half_rn(w);
        float lo = w - __half2float(h);
        g_Bhi[n*136 + k] = h;
        g_Blo[n*136 + k] = __float2half_rn(lo);
    } else if (idx < 128*128 + 128*16){
        int r = idx - 128*128;
        int k = r >> 4, c = r & 15;
        float w = We2[k*16 + c];
        __nv_bfloat16 h = __float2bfloat16_rn(w);
        float lo = w - __bfloat162float(h);
        g_W2hi[c*136 + k] = h;
        g_W2lo[c*136 + k] = __float2bfloat16_rn(lo);
    }
}

// ---------------------------------------------------------------------------
// K3: edge MLP. GEMM1: A single fp16, B (We1^T) 2-split fp16 -> 2 MMA terms.
// GEMM2: bf16 3-split chained from accumulators. Tile = 128 pairs (8i x 16j).
// ---------------------------------------------------------------------------
#define OFF_BHI  0                    // 34816
#define OFF_BLO  34816                // 34816
#define OFF_W2HI 69632                // 4352
#define OFF_W2LO 73984                // 4352
#define OFF_BE1  78336                // 512
#define OFF_BE2  78848                // 64
#define OFF_STG  78912                // A0s[8][132] + B0s[16][132] = 12672
#define OFF_A0S  OFF_STG
#define OFF_B0S  (OFF_STG + 8*132*4)
#define OFF_ES   OFF_STG              // alias: [128][20] f = 10240
#define K3_SMEM  (OFF_STG + 12672)    // 91584 B -> 2 CTAs/SM

__global__ void __launch_bounds__(256, 2)
k3_edge_mma(const float* __restrict__ be0,
            const float* __restrict__ be1,
            const float* __restrict__ be2,
            float* __restrict__ U)
{
    extern __shared__ char smem[];
    float* smemf = reinterpret_cast<float*>(smem);
    const uint32_t sb = smem_u32(smem);
    const int tid = threadIdx.x;
    const int wid = tid >> 5;
    const int lane = tid & 31;
    const int g = lane >> 2;
    const int r = lane & 3;

    // triangular tile decode: jt s.t. jt(jt+1) <= t < (jt+1)(jt+2)
    const int t = blockIdx.x;
    int jt = 0;
#pragma unroll
    for (int q=1;q<8;q++) if (t >= q*(q+1)) jt = q;
    const int it = t - jt*(jt+1);
    const int b  = blockIdx.y;
    const int i0 = it*8, j0 = jt*16;

    // ---- stage weights + A0/B0 rows ----
    {
        const uint4* sh  = reinterpret_cast<const uint4*>(g_Bhi);
        const uint4* sl  = reinterpret_cast<const uint4*>(g_Blo);
        uint4* dh = reinterpret_cast<uint4*>(smem + OFF_BHI);
        uint4* dl = reinterpret_cast<uint4*>(smem + OFF_BLO);
        for (int l = tid; l < 2176; l += 256){ dh[l] = sh[l]; dl[l] = sl[l]; }
        const uint4* s2h = reinterpret_cast<const uint4*>(g_W2hi);
        const uint4* s2l = reinterpret_cast<const uint4*>(g_W2lo);
        uint4* d2h = reinterpret_cast<uint4*>(smem + OFF_W2HI);
        uint4* d2l = reinterpret_cast<uint4*>(smem + OFF_W2LO);
        for (int l = tid; l < 272; l += 256){ d2h[l] = s2h[l]; d2l[l] = s2l[l]; }
        if (tid < 128) smemf[OFF_BE1/4 + tid] = be1[tid];
        else if (tid < 144) smemf[OFF_BE2/4 + tid - 128] = be2[tid - 128];
        // A0s: 8 rows x 128 f (no be0); B0s: 16 rows x 128 f (+be0)
        for (int l = tid; l < 256; l += 256){
            int rr = l >> 5, c4 = (l & 31)*4;
            float4 v = *reinterpret_cast<const float4*>(g_A0 + ((size_t)(b*NN + i0 + rr))*128 + c4);
            *reinterpret_cast<float4*>(smemf + OFF_A0S/4 + rr*132 + c4) = v;
        }
        for (int l = tid; l < 512; l += 256){
            int rr = l >> 5, c4 = (l & 31)*4;
            float4 v  = *reinterpret_cast<const float4*>(g_B0 + ((size_t)(b*NN + j0 + rr))*128 + c4);
            float4 e0 = *reinterpret_cast<const float4*>(be0 + c4);
            v.x += e0.x; v.y += e0.y; v.z += e0.z; v.w += e0.w;
            *reinterpret_cast<float4*>(smemf + OFF_B0S/4 + rr*132 + c4) = v;
        }
    }
    __syncthreads();

    const int mg = wid >> 1;       // 0..3 -> rows mg*32..+31
    const int ng = wid & 1;        // 0..1 -> cols ng*64..+63
    float acc[2][8][4];
#pragma unroll
    for (int a1=0;a1<2;a1++)
#pragma unroll
        for (int a2=0;a2<8;a2++)
#pragma unroll
            for (int a3=0;a3<4;a3++) acc[a1][a2][a3] = 0.f;

    // ---- GEMM1: register-built fp16 A (t0), ldmatrix fp16 B hi/lo ----
    {
        const uint32_t bOff = (uint32_t)((ng*64 + ((lane >> 4) << 3) + (lane & 7))*272
                                        + ((lane >> 3) & 1)*16);
        const uint32_t bHi = sb + OFF_BHI + bOff, bLo = sb + OFF_BLO + bOff;
        const float* A0p = smemf + OFF_A0S/4;
        const float* B0p = smemf + OFF_B0S/4;

#pragma unroll
        for (int ks = 0; ks < 8; ks++){
            // B0 rows j = g, g+8 (shared across mt)
            float2 b00 = *reinterpret_cast<const float2*>(B0p + g*132      + ks*16 + 2*r);
            float2 b01 = *reinterpret_cast<const float2*>(B0p + g*132      + ks*16 + 8 + 2*r);
            float2 b10 = *reinterpret_cast<const float2*>(B0p + (g+8)*132  + ks*16 + 2*r);
            float2 b11 = *reinterpret_cast<const float2*>(B0p + (g+8)*132  + ks*16 + 8 + 2*r);

            uint32_t ah[2][4];
#pragma unroll
            for (int mt=0; mt<2; mt++){
                const float* Ar = A0p + (mg*2+mt)*132 + ks*16;
                float2 ak0 = *reinterpret_cast<const float2*>(Ar + 2*r);
                float2 ak1 = *reinterpret_cast<const float2*>(Ar + 8 + 2*r);
                ah[mt][0] = packh2(lrelu(ak0.x+b00.x), lrelu(ak0.y+b00.y));
                ah[mt][1] = packh2(lrelu(ak0.x+b10.x), lrelu(ak0.y+b10.y));
                ah[mt][2] = packh2(lrelu(ak1.x+b01.x), lrelu(ak1.y+b01.y));
                ah[mt][3] = packh2(lrelu(ak1.x+b11.x), lrelu(ak1.y+b11.y));
            }
#pragma unroll
            for (int n2 = 0; n2 < 4; n2++){
                uint32_t bh[4], bl[4];
                LDM4(bh, bHi + n2*4352 + ks*32);
                LDM4(bl, bLo + n2*4352 + ks*32);
                MMA16816H(acc[0][2*n2],   ah[0], bh[0], bh[1]);
                MMA16816H(acc[0][2*n2],   ah[0], bl[0], bl[1]);
                MMA16816H(acc[0][2*n2+1], ah[0], bh[2], bh[3]);
                MMA16816H(acc[0][2*n2+1], ah[0], bl[2], bl[3]);
                MMA16816H(acc[1][2*n2],   ah[1], bh[0], bh[1]);
                MMA16816H(acc[1][2*n2],   ah[1], bl[0], bl[1]);
                MMA16816H(acc[1][2*n2+1], ah[1], bh[2], bh[3]);
                MMA16816H(acc[1][2*n2+1], ah[1], bl[2], bl[3]);
            }
        }
    }

    // ---- GEMM2: chain acc -> t1 A-fragments (bf16 3-split), partial e ----
    float e[2][2][4];
#pragma unroll
    for (int a1=0;a1<2;a1++)
#pragma unroll
        for (int a2=0;a2<2;a2++)
#pragma unroll
            for (int a3=0;a3<4;a3++) e[a1][a2][a3] = 0.f;

    {
        const uint32_t b2Off = (uint32_t)(((((lane >> 4) << 3) + (lane & 7))*272)
                                        + ((lane >> 3) & 1)*16);
        const uint32_t wHi = sb + OFF_W2HI + b2Off, wLo = sb + OFF_W2LO + b2Off;

#pragma unroll
        for (int qk = 0; qk < 4; qk++){
            uint32_t bh[4], bl[4];
            LDM4(bh, wHi + (ng*4+qk)*32);
            LDM4(bl, wLo + (ng*4+qk)*32);
#pragma unroll
            for (int mt = 0; mt < 2; mt++){
                const int ntA = 2*qk, ntB = 2*qk+1;
                const int cA = ng*64 + ntA*8 + 2*r;
                const int cB = ng*64 + ntB*8 + 2*r;
                float beA0 = smemf[OFF_BE1/4 + cA], beA1 = smemf[OFF_BE1/4 + cA + 1];
                float beB0 = smemf[OFF_BE1/4 + cB], beB1 = smemf[OFF_BE1/4 + cB + 1];
                uint32_t ah[4], al[4];
                split2(lrelu(acc[mt][ntA][0]+beA0), lrelu(acc[mt][ntA][1]+beA1), ah[0], al[0]);
                split2(lrelu(acc[mt][ntA][2]+beA0), lrelu(acc[mt][ntA][3]+beA1), ah[1], al[1]);
                split2(lrelu(acc[mt][ntB][0]+beB0), lrelu(acc[mt][ntB][1]+beB1), ah[2], al[2]);
                split2(lrelu(acc[mt][ntB][2]+beB0), lrelu(acc[mt][ntB][3]+beB1), ah[3], al[3]);
                MMA16816(e[mt][0], ah, bh[0], bh[1]);
                MMA16816(e[mt][0], al, bh[0], bh[1]);
                MMA16816(e[mt][0], ah, bl[0], bl[1]);
                MMA16816(e[mt][1], ah, bh[2], bh[3]);
                MMA16816(e[mt][1], al, bh[2], bh[3]);
                MMA16816(e[mt][1], ah, bl[2], bl[3]);
            }
        }
    }

    // ---- cross-warp (ng pair) reduction + scatter into U ----
    __syncthreads();   // A0s/B0s reads done; safe to overwrite with ES
    float* es = smemf + OFF_ES/4;   // [128][20]

    if (ng == 1){
#pragma unroll
        for (int mt=0; mt<2; mt++)
#pragma unroll
        for (int t_=0; t_<2; t_++)
#pragma unroll
        for (int rh=0; rh<2; rh++){
            int row = mg*32 + mt*16 + g + rh*8;
            int c = t_*8 + 2*r;
            *reinterpret_cast<float2*>(&es[row*20 + c]) =
                make_float2(e[mt][t_][rh*2+0], e[mt][t_][rh*2+1]);
        }
    }
    __syncthreads();
    if (ng == 0){
        float* Ub = U + (size_t)b*U_PER_B;
#pragma unroll
        for (int mt=0; mt<2; mt++)
#pragma unroll
        for (int t_=0; t_<2; t_++)
#pragma unroll
        for (int rh=0; rh<2; rh++){
            int row = mg*32 + mt*16 + g + rh*8;
            int c = t_*8 + 2*r;
            float2 part = *reinterpret_cast<const float2*>(&es[row*20 + c]);
            float vx = e[mt][t_][rh*2+0] + part.x + smemf[OFF_BE2/4 + c];
            float vy = e[mt][t_][rh*2+1] + part.y + smemf[OFF_BE2/4 + c + 1];
            int i = i0 + (row >> 4);
            int j = j0 + (row & 15);
            if (i < j){
                int qq = c >> 2, m = c & 3;
                float2 v2 = make_float2(vx, vy);
                *reinterpret_cast<float2*>(Ub + (size_t)(4*i+qq)*U_STRIDE + 4*j + m) = v2;
                *reinterpret_cast<float2*>(Ub + (size_t)(4*j+qq)*U_STRIDE + 4*i + m) = v2;
            }
        }
    }
}

// ---------------------------------------------------------------------------
extern "C" void kernel_launch(void* const* d_in, const int* in_sizes, int n_in,
                              void* d_out, int out_size)
{
    const float* x   = (const float*)d_in[0];
    const float* Wg0 = (const float*)d_in[4];
    const float* bg0 = (const float*)d_in[5];
    const float* Wg1 = (const float*)d_in[6];
    const float* bg1 = (const float*)d_in[7];
    const float* Wg2 = (const float*)d_in[8];
    const float* bg2 = (const float*)d_in[9];
    const float* Wn0 = (const float*)d_in[10];
    const float* bn0 = (const float*)d_in[11];
    const float* Wn1 = (const float*)d_in[12];
    const float* bn1 = (const float*)d_in[13];
    const float* Wn2 = (const float*)d_in[14];
    const float* bn2 = (const float*)d_in[15];
    const float* We0 = (const float*)d_in[16];
    const float* be0 = (const float*)d_in[17];
    const float* We1 = (const float*)d_in[18];
    const float* be1 = (const float*)d_in[19];
    const float* We2 = (const float*)d_in[20];
    const float* be2 = (const float*)d_in[21];

    float* h_out = (float*)d_out;                 // (16384, 64)
    float* U     = h_out + (size_t)TOTAL*D_MP;    // (128, 512, 512)

    static bool attr_set = false;
    if (!attr_set){
        cudaFuncSetAttribute(k3_edge_mma, cudaFuncAttributeMaxDynamicSharedMemorySize, K3_SMEM);
        cudaFuncSetAttribute(k2b_node, cudaFuncAttributeMaxDynamicSharedMemorySize, K2B_SMEM);
        attr_set = true;
    }

    k_prep<<<72, 256>>>(We1, We2);
    k1_gcn<<<BATCH, 128>>>(x, Wg0,bg0, Wg1,bg1, Wg2,bg2, h_out);
    k2_ab<<<TOTAL/32, 256>>>(h_out, We0);
    k2b_node<<<512, 256, K2B_SMEM>>>(h_out, Wn0,bn0, Wn1,bn1, Wn2,bn2, U);
    k3_edge_mma<<<dim3(72, BATCH), 256, K3_SMEM>>>(be0, be1, be2, U);
}